// round 6
// baseline (speedup 1.0000x reference)
#include <cuda_runtime.h>
#include <math.h>

// ---------------------------------------------------------------------------
// NUFFT adjoint (Kaiser-Bessel gridding) for GB300 — round 6
// R5 + (a) zero_kernel eliminated: grid re-zeroing fused into FFT passes
// (grid is all-zero at end of every launch; scatter lands on zeros),
// (b) stage-4 output pruning (only fftshift+crop-surviving halves computed).
// ---------------------------------------------------------------------------

#define KGRID   1024
#define NIMG    512
#define MPTS    200000
#define BATCH   8
#define JW      6
#define BETA_F  14.04f
#define PI_F    3.14159265358979f

#define GRID_F2 (KGRID * KGRID * BATCH)   // 64 MB
#define PITCH   1026                      // smem row pitch (float2), even

// packed twiddle table: per stage s=1..4, entries [off + 3*j + k], k=0..2
#define TW_OFF1 0
#define TW_OFF2 12
#define TW_OFF3 60
#define TW_OFF4 252
#define TW_TOT  1020

__device__ float2 g_grid[GRID_F2];        // zero-initialized at module load

// ---------------------------------------------------------------------------
__device__ __forceinline__ float bessel_i0(float x)
{
    if (x < 3.75f) {
        float t = x * (1.0f / 3.75f);
        t *= t;
        return 1.0f + t * (3.5156229f + t * (3.0899424f + t * (1.2067492f +
                     t * (0.2659732f + t * (0.0360768f + t * 0.0045813f)))));
    } else {
        float t = 3.75f / x;
        float p = 0.39894228f + t * (0.01328592f + t * (0.00225319f +
                  t * (-0.00157565f + t * (0.00916281f + t * (-0.02057706f +
                  t * (0.02635537f + t * (-0.01647633f + t * 0.00392377f)))))));
        return __expf(x) * rsqrtf(x) * p;
    }
}

// ---------------------------------------------------------------------------
__global__ __launch_bounds__(256)
void scatter_kernel(const float* __restrict__ yr, const float* __restrict__ yi,
                    const float* __restrict__ uv, const float* __restrict__ wts)
{
    int m = blockIdx.x * blockDim.x + threadIdx.x;
    if (m >= MPTS) return;

    const float2 c2 = reinterpret_cast<const float2*>(uv)[m];
    const float wt = wts[m];
    const float inv_i0b = 1.0f / bessel_i0(BETA_F);

    int ixv[JW], iyv[JW];
    float wx[JW], wy[JW];

    {
        float k  = c2.x / (2.0f * PI_F) * (float)KGRID;
        float km = floorf(k - 3.0f);
        #pragma unroll
        for (int j = 0; j < JW; j++) {
            float pt = km + (float)(j + 1);
            float d  = k - pt;
            float arg = fmaxf(1.0f - d * d * (1.0f / 9.0f), 0.0f);
            wx[j] = bessel_i0(BETA_F * sqrtf(arg)) * inv_i0b;
            ixv[j] = ((int)pt + KGRID) & (KGRID - 1);
        }
    }
    {
        float k  = c2.y / (2.0f * PI_F) * (float)KGRID;
        float km = floorf(k - 3.0f);
        #pragma unroll
        for (int j = 0; j < JW; j++) {
            float pt = km + (float)(j + 1);
            float d  = k - pt;
            float arg = fmaxf(1.0f - d * d * (1.0f / 9.0f), 0.0f);
            wy[j] = bessel_i0(BETA_F * sqrtf(arg)) * inv_i0b;
            iyv[j] = ((int)pt + KGRID) & (KGRID - 1);
        }
    }

    float yrw[BATCH], yiw[BATCH];
    #pragma unroll
    for (int b = 0; b < BATCH; b++) {
        yrw[b] = yr[b * MPTS + m] * wt;
        yiw[b] = yi[b * MPTS + m] * wt;
    }

    #pragma unroll
    for (int a = 0; a < JW; a++) {
        const int rowbase = ixv[a] * KGRID;
        const float wxa = wx[a];
        #pragma unroll
        for (int c = 0; c < JW; c++) {
            const float w2 = wxa * wy[c];
            float* fp = reinterpret_cast<float*>(&g_grid[(rowbase + iyv[c]) * BATCH]);
            #pragma unroll
            for (int b = 0; b < BATCH; b += 2) {
                asm volatile(
                    "red.global.add.v4.f32 [%0], {%1, %2, %3, %4};"
                    :: "l"(fp + 2 * b),
                       "f"(w2 * yrw[b]),     "f"(w2 * yiw[b]),
                       "f"(w2 * yrw[b + 1]), "f"(w2 * yiw[b + 1])
                    : "memory");
            }
        }
    }
}

// ---------------------------------------------------------------------------
// Radix-4 FFT machinery (inverse, e^{+i})
// ---------------------------------------------------------------------------
__device__ __forceinline__ int digit_rev10(int i)
{
    int r = (int)(__brev((unsigned)i) >> 22);
    return ((r & 0x155) << 1) | ((r & 0x2AA) >> 1);
}

__device__ __forceinline__ float2 cmul(float2 a, float2 b)
{
    return make_float2(a.x * b.x - a.y * b.y, a.x * b.y + a.y * b.x);
}

__device__ __forceinline__ void init_tw(float2* tw, int tid, int nthr)
{
    for (int t = tid; t < 340; t += nthr) {
        int s, j, off;
        if      (t < 4)  { s = 1; j = t;      off = TW_OFF1; }
        else if (t < 20) { s = 2; j = t - 4;  off = TW_OFF2; }
        else if (t < 84) { s = 3; j = t - 20; off = TW_OFF3; }
        else             { s = 4; j = t - 84; off = TW_OFF4; }
        int em = j << (8 - 2 * s);
        float a = (float)em * (2.0f * PI_F / 1024.0f);
        float s1, c1, s2, c2, s3, c3;
        __sincosf(a, &s1, &c1);
        __sincosf(2.0f * a, &s2, &c2);
        __sincosf(3.0f * a, &s3, &c3);
        tw[off + 3 * j + 0] = make_float2(c1, s1);
        tw[off + 3 * j + 1] = make_float2(c2, s2);
        tw[off + 3 * j + 2] = make_float2(c3, s3);
    }
}

__device__ __forceinline__ void rad4(float2 b0, float2 b1, float2 b2, float2 b3,
                                     float2& y0, float2& y1, float2& y2, float2& y3)
{
    float2 t0 = make_float2(b0.x + b2.x, b0.y + b2.y);
    float2 t1 = make_float2(b0.x - b2.x, b0.y - b2.y);
    float2 t2 = make_float2(b1.x + b3.x, b1.y + b3.y);
    float2 t3 = make_float2(-(b1.y - b3.y), b1.x - b3.x);   // +i*(b1-b3)
    y0 = make_float2(t0.x + t2.x, t0.y + t2.y);
    y1 = make_float2(t1.x + t3.x, t1.y + t3.y);
    y2 = make_float2(t0.x - t2.x, t0.y - t2.y);
    y3 = make_float2(t1.x - t3.x, t1.y - t3.y);
}

template<int S, int OFF>
__device__ __forceinline__ void stage4(float2* x, const float2* tw, int bi0)
{
    const int sh = 2 * S;
    const int quarter = 1 << sh;
    #pragma unroll
    for (int u = 0; u < 4; u++) {
        const int bi = bi0 + (u << 6);
        const int j  = bi & (quarter - 1);
        const int base = ((bi >> sh) << (sh + 2)) | j;
        float2 b0 = x[base];
        float2 b1 = x[base + quarter];
        float2 b2 = x[base + 2 * quarter];
        float2 b3 = x[base + 3 * quarter];
        b1 = cmul(b1, tw[OFF + 3 * j + 0]);
        b2 = cmul(b2, tw[OFF + 3 * j + 1]);
        b3 = cmul(b3, tw[OFF + 3 * j + 2]);
        float2 y0, y1, y2, y3;
        rad4(b0, b1, b2, b3, y0, y1, y2, y3);
        x[base]               = y0;
        x[base + quarter]     = y1;
        x[base + 2 * quarter] = y2;
        x[base + 3 * quarter] = y3;
    }
}

// Final stage (S=4), pruned: only outputs in [0,256) (y0) and [768,1024) (y3)
// survive fftshift+crop in both FFT passes.
__device__ __forceinline__ void stage4_last_pruned(float2* x, const float2* tw,
                                                   int bi0)
{
    const int quarter = 256;
    #pragma unroll
    for (int u = 0; u < 4; u++) {
        const int j = bi0 + (u << 6);          // base == j for S=4
        float2 b0 = x[j];
        float2 b1 = cmul(x[j + quarter],     tw[TW_OFF4 + 3 * j + 0]);
        float2 b2 = cmul(x[j + 2 * quarter], tw[TW_OFF4 + 3 * j + 1]);
        float2 b3 = cmul(x[j + 3 * quarter], tw[TW_OFF4 + 3 * j + 2]);
        float2 t0 = make_float2(b0.x + b2.x, b0.y + b2.y);
        float2 t1 = make_float2(b0.x - b2.x, b0.y - b2.y);
        float2 t2 = make_float2(b1.x + b3.x, b1.y + b3.y);
        float2 t3 = make_float2(-(b1.y - b3.y), b1.x - b3.x);
        x[j]               = make_float2(t0.x + t2.x, t0.y + t2.y);  // y0
        x[j + 3 * quarter] = make_float2(t1.x - t3.x, t1.y - t3.y);  // y3
    }
}

// 8 independent 1024-pt inverse FFTs; 512 threads; rows pitch PITCH.
__device__ __forceinline__ void fft8x1024(float2* data, const float2* tw, int tid)
{
    {   // stage 0: float4-vectorized, twiddle-free, fft-major
        float4* xv = reinterpret_cast<float4*>(data + (tid & 7) * PITCH);
        const int bi0 = tid >> 3;
        #pragma unroll
        for (int u = 0; u < 4; u++) {
            const int bi = bi0 + (u << 6);
            float4 f01 = xv[2 * bi];
            float4 f23 = xv[2 * bi + 1];
            float2 y0, y1, y2, y3;
            rad4(make_float2(f01.x, f01.y), make_float2(f01.z, f01.w),
                 make_float2(f23.x, f23.y), make_float2(f23.z, f23.w),
                 y0, y1, y2, y3);
            xv[2 * bi]     = make_float4(y0.x, y0.y, y1.x, y1.y);
            xv[2 * bi + 1] = make_float4(y2.x, y2.y, y3.x, y3.y);
        }
        __syncthreads();
    }
    stage4<1, TW_OFF1>(data + (tid & 7) * PITCH, tw, tid >> 3);
    __syncthreads();
    stage4<2, TW_OFF2>(data + (tid >> 6) * PITCH, tw, tid & 63);
    __syncthreads();
    stage4<3, TW_OFF3>(data + (tid >> 6) * PITCH, tw, tid & 63);
    __syncthreads();
    stage4_last_pruned(data + (tid >> 6) * PITCH, tw, tid & 63);
    __syncthreads();
}

// ---------------------------------------------------------------------------
// FFT along kx. Block = one iy (8 batch FFTs). Pruned output rows.
// Fused zeroing: rows 256-767 of g_grid are zeroed right after being read.
// ---------------------------------------------------------------------------
__global__ __launch_bounds__(512, 3)
void fft_x_kernel()
{
    extern __shared__ float2 sm[];
    float2* tw   = sm;
    float2* data = sm + TW_TOT;
    const int tid = threadIdx.x;
    init_tw(tw, tid, 512);

    const int iy = blockIdx.x;

    for (int t = tid; t < 8 * KGRID; t += 512) {
        int ix = t >> 3;
        int c  = t & 7;
        float2* gp = &g_grid[ix * (KGRID * BATCH) + iy * BATCH + c];
        float2 v = *gp;
        if (ix >= 256 && ix < 768)
            *gp = make_float2(0.f, 0.f);       // restore zero for next launch
        data[c * PITCH + digit_rev10(ix)] = v;
    }
    __syncthreads();

    fft8x1024(data, tw, tid);

    for (int t = tid; t < 8 * 512; t += 512) {
        int xl = t >> 3;
        int c  = t & 7;
        int xg = (xl < 256) ? xl : xl + 512;   // rows kept after shift+crop
        g_grid[xg * (KGRID * BATCH) + iy * BATCH + c] = data[c * PITCH + xg];
    }
}

// ---------------------------------------------------------------------------
__device__ __forceinline__ float inv_apod(int i)
{
    float xv = ((float)i - 256.0f) * (1.0f / 1024.0f);
    float pj = PI_F * 6.0f * xv;
    float tv = BETA_F * BETA_F - pj * pj;
    float st = sqrtf(fabsf(tv));
    float num = (tv > 0.0f) ? sinhf(st) : sinf(st);
    return fmaxf(st, 1e-6f) / num;
}

// FFT along ky for one surviving x row + fused epilogue.
// Fused zeroing: the row is zeroed right after being read.
__global__ __launch_bounds__(512, 3)
void fft_y_kernel(float* __restrict__ out)
{
    extern __shared__ float2 sm[];
    float2* tw   = sm;
    float2* data = sm + TW_TOT;
    const int tid = threadIdx.x;
    init_tw(tw, tid, 512);

    const int x_img = blockIdx.x;
    const int x_src = (x_img + 768) & (KGRID - 1);
    float2* grow = &g_grid[x_src * (KGRID * BATCH)];

    for (int t = tid; t < 8 * KGRID; t += 512) {
        int iy = t >> 3;
        int c  = t & 7;
        float2 v = grow[t];
        grow[t] = make_float2(0.f, 0.f);       // restore zero for next launch
        data[c * PITCH + digit_rev10(iy)] = v;
    }
    __syncthreads();

    fft8x1024(data, tw, tid);

    const float iax = inv_apod(x_img);
    for (int t = tid; t < 8 * NIMG; t += 512) {
        int b  = t >> 9;
        int yi = t & 511;
        int ys = (yi + 768) & (KGRID - 1);     // in [0,256) U [768,1024): valid
        float v = data[b * PITCH + ys].x;
        out[b * (NIMG * NIMG) + x_img * NIMG + yi] = v * iax * inv_apod(yi);
    }
}

// ---------------------------------------------------------------------------
extern "C" void kernel_launch(void* const* d_in, const int* in_sizes, int n_in,
                              void* d_out, int out_size)
{
    const float* yr  = (const float*)d_in[0];
    const float* yi  = (const float*)d_in[1];
    const float* uv  = (const float*)d_in[2];
    const float* wts = (const float*)d_in[3];
    float* out = (float*)d_out;

    const int smem_fft = (TW_TOT + 8 * PITCH) * (int)sizeof(float2); // ~73.8 KB
    cudaFuncSetAttribute(fft_x_kernel,
                         cudaFuncAttributeMaxDynamicSharedMemorySize, smem_fft);
    cudaFuncSetAttribute(fft_y_kernel,
                         cudaFuncAttributeMaxDynamicSharedMemorySize, smem_fft);

    scatter_kernel<<<(MPTS + 255) / 256, 256>>>(yr, yi, uv, wts);
    fft_x_kernel<<<KGRID, 512, smem_fft>>>();
    fft_y_kernel<<<NIMG, 512, smem_fft>>>(out);
}

// round 7
// speedup vs baseline: 2.5064x; 2.5064x over previous
#include <cuda_runtime.h>
#include <math.h>

// ---------------------------------------------------------------------------
// NUFFT adjoint (Kaiser-Bessel gridding) for GB300 — round 7
// = R5 structure (zero_kernel restored: it keeps the grid L2-resident for the
//   scatter's L2 atomics — removing it cost 185us in R6)
// + stage-4 output pruning (kept from R6)
// + scatter split 4-ways per point (2 batches/thread) for atomic MLP.
// ---------------------------------------------------------------------------

#define KGRID   1024
#define NIMG    512
#define MPTS    200000
#define BATCH   8
#define JW      6
#define BETA_F  14.04f
#define PI_F    3.14159265358979f

#define GRID_F2 (KGRID * KGRID * BATCH)   // 64 MB
#define PITCH   1026                      // smem row pitch (float2), even

#define TW_OFF1 0
#define TW_OFF2 12
#define TW_OFF3 60
#define TW_OFF4 252
#define TW_TOT  1020

__device__ float2 g_grid[GRID_F2];

// ---------------------------------------------------------------------------
__device__ __forceinline__ float bessel_i0(float x)
{
    if (x < 3.75f) {
        float t = x * (1.0f / 3.75f);
        t *= t;
        return 1.0f + t * (3.5156229f + t * (3.0899424f + t * (1.2067492f +
                     t * (0.2659732f + t * (0.0360768f + t * 0.0045813f)))));
    } else {
        float t = 3.75f / x;
        float p = 0.39894228f + t * (0.01328592f + t * (0.00225319f +
                  t * (-0.00157565f + t * (0.00916281f + t * (-0.02057706f +
                  t * (0.02635537f + t * (-0.01647633f + t * 0.00392377f)))))));
        return __expf(x) * rsqrtf(x) * p;
    }
}

// ---------------------------------------------------------------------------
// Zero the oversampled grid. Also acts as an L2 prefetch/warm for the
// scatter's atomics: all 64 MB become dirty-zero L2 lines.
// ---------------------------------------------------------------------------
__global__ void zero_kernel()
{
    float4* p = reinterpret_cast<float4*>(g_grid);
    const int n = GRID_F2 / 2;
    for (int i = blockIdx.x * blockDim.x + threadIdx.x; i < n;
         i += gridDim.x * blockDim.x)
        p[i] = make_float4(0.f, 0.f, 0.f, 0.f);
}

// ---------------------------------------------------------------------------
// Gridding scatter: 4 threads per measurement, 2 batches per thread.
// 36 taps x 1 red.v4.f32 per thread.
// ---------------------------------------------------------------------------
__global__ __launch_bounds__(256)
void scatter_kernel(const float* __restrict__ yr, const float* __restrict__ yi,
                    const float* __restrict__ uv, const float* __restrict__ wts)
{
    const int gid = blockIdx.x * blockDim.x + threadIdx.x;
    const int m = gid >> 2;
    const int q = gid & 3;                 // batch pair: 2q, 2q+1
    if (m >= MPTS) return;

    const float2 c2 = reinterpret_cast<const float2*>(uv)[m];
    const float wt = wts[m];
    const float inv_i0b = 1.0f / bessel_i0(BETA_F);

    int ixv[JW], iyv[JW];
    float wx[JW], wy[JW];

    {
        float k  = c2.x / (2.0f * PI_F) * (float)KGRID;
        float km = floorf(k - 3.0f);
        #pragma unroll
        for (int j = 0; j < JW; j++) {
            float pt = km + (float)(j + 1);
            float d  = k - pt;
            float arg = fmaxf(1.0f - d * d * (1.0f / 9.0f), 0.0f);
            wx[j] = bessel_i0(BETA_F * sqrtf(arg)) * inv_i0b;
            ixv[j] = ((int)pt + KGRID) & (KGRID - 1);
        }
    }
    {
        float k  = c2.y / (2.0f * PI_F) * (float)KGRID;
        float km = floorf(k - 3.0f);
        #pragma unroll
        for (int j = 0; j < JW; j++) {
            float pt = km + (float)(j + 1);
            float d  = k - pt;
            float arg = fmaxf(1.0f - d * d * (1.0f / 9.0f), 0.0f);
            wy[j] = bessel_i0(BETA_F * sqrtf(arg)) * inv_i0b;
            iyv[j] = ((int)pt + KGRID) & (KGRID - 1);
        }
    }

    const int b0 = 2 * q;
    const float yr0 = yr[b0 * MPTS + m] * wt;
    const float yi0 = yi[b0 * MPTS + m] * wt;
    const float yr1 = yr[(b0 + 1) * MPTS + m] * wt;
    const float yi1 = yi[(b0 + 1) * MPTS + m] * wt;

    #pragma unroll
    for (int a = 0; a < JW; a++) {
        const int rowbase = ixv[a] * KGRID;
        const float wxa = wx[a];
        #pragma unroll
        for (int c = 0; c < JW; c++) {
            const float w2 = wxa * wy[c];
            float* fp = reinterpret_cast<float*>(&g_grid[(rowbase + iyv[c]) * BATCH])
                        + 4 * q;
            asm volatile(
                "red.global.add.v4.f32 [%0], {%1, %2, %3, %4};"
                :: "l"(fp),
                   "f"(w2 * yr0), "f"(w2 * yi0),
                   "f"(w2 * yr1), "f"(w2 * yi1)
                : "memory");
        }
    }
}

// ---------------------------------------------------------------------------
// Radix-4 FFT machinery (inverse, e^{+i})
// ---------------------------------------------------------------------------
__device__ __forceinline__ int digit_rev10(int i)
{
    int r = (int)(__brev((unsigned)i) >> 22);
    return ((r & 0x155) << 1) | ((r & 0x2AA) >> 1);
}

__device__ __forceinline__ float2 cmul(float2 a, float2 b)
{
    return make_float2(a.x * b.x - a.y * b.y, a.x * b.y + a.y * b.x);
}

__device__ __forceinline__ void init_tw(float2* tw, int tid, int nthr)
{
    for (int t = tid; t < 340; t += nthr) {
        int s, j, off;
        if      (t < 4)  { s = 1; j = t;      off = TW_OFF1; }
        else if (t < 20) { s = 2; j = t - 4;  off = TW_OFF2; }
        else if (t < 84) { s = 3; j = t - 20; off = TW_OFF3; }
        else             { s = 4; j = t - 84; off = TW_OFF4; }
        int em = j << (8 - 2 * s);
        float a = (float)em * (2.0f * PI_F / 1024.0f);
        float s1, c1, s2, c2, s3, c3;
        __sincosf(a, &s1, &c1);
        __sincosf(2.0f * a, &s2, &c2);
        __sincosf(3.0f * a, &s3, &c3);
        tw[off + 3 * j + 0] = make_float2(c1, s1);
        tw[off + 3 * j + 1] = make_float2(c2, s2);
        tw[off + 3 * j + 2] = make_float2(c3, s3);
    }
}

__device__ __forceinline__ void rad4(float2 b0, float2 b1, float2 b2, float2 b3,
                                     float2& y0, float2& y1, float2& y2, float2& y3)
{
    float2 t0 = make_float2(b0.x + b2.x, b0.y + b2.y);
    float2 t1 = make_float2(b0.x - b2.x, b0.y - b2.y);
    float2 t2 = make_float2(b1.x + b3.x, b1.y + b3.y);
    float2 t3 = make_float2(-(b1.y - b3.y), b1.x - b3.x);   // +i*(b1-b3)
    y0 = make_float2(t0.x + t2.x, t0.y + t2.y);
    y1 = make_float2(t1.x + t3.x, t1.y + t3.y);
    y2 = make_float2(t0.x - t2.x, t0.y - t2.y);
    y3 = make_float2(t1.x - t3.x, t1.y - t3.y);
}

template<int S, int OFF>
__device__ __forceinline__ void stage4(float2* x, const float2* tw, int bi0)
{
    const int sh = 2 * S;
    const int quarter = 1 << sh;
    #pragma unroll
    for (int u = 0; u < 4; u++) {
        const int bi = bi0 + (u << 6);
        const int j  = bi & (quarter - 1);
        const int base = ((bi >> sh) << (sh + 2)) | j;
        float2 b0 = x[base];
        float2 b1 = x[base + quarter];
        float2 b2 = x[base + 2 * quarter];
        float2 b3 = x[base + 3 * quarter];
        b1 = cmul(b1, tw[OFF + 3 * j + 0]);
        b2 = cmul(b2, tw[OFF + 3 * j + 1]);
        b3 = cmul(b3, tw[OFF + 3 * j + 2]);
        float2 y0, y1, y2, y3;
        rad4(b0, b1, b2, b3, y0, y1, y2, y3);
        x[base]               = y0;
        x[base + quarter]     = y1;
        x[base + 2 * quarter] = y2;
        x[base + 3 * quarter] = y3;
    }
}

// Final stage (S=4), pruned: only outputs in [0,256) (y0) and [768,1024) (y3)
// survive fftshift+crop in both FFT passes.
__device__ __forceinline__ void stage4_last_pruned(float2* x, const float2* tw,
                                                   int bi0)
{
    const int quarter = 256;
    #pragma unroll
    for (int u = 0; u < 4; u++) {
        const int j = bi0 + (u << 6);          // base == j for S=4
        float2 b0 = x[j];
        float2 b1 = cmul(x[j + quarter],     tw[TW_OFF4 + 3 * j + 0]);
        float2 b2 = cmul(x[j + 2 * quarter], tw[TW_OFF4 + 3 * j + 1]);
        float2 b3 = cmul(x[j + 3 * quarter], tw[TW_OFF4 + 3 * j + 2]);
        float2 t0 = make_float2(b0.x + b2.x, b0.y + b2.y);
        float2 t1 = make_float2(b0.x - b2.x, b0.y - b2.y);
        float2 t2 = make_float2(b1.x + b3.x, b1.y + b3.y);
        float2 t3 = make_float2(-(b1.y - b3.y), b1.x - b3.x);
        x[j]               = make_float2(t0.x + t2.x, t0.y + t2.y);  // y0
        x[j + 3 * quarter] = make_float2(t1.x - t3.x, t1.y - t3.y);  // y3
    }
}

__device__ __forceinline__ void fft8x1024(float2* data, const float2* tw, int tid)
{
    {   // stage 0: float4-vectorized, twiddle-free, fft-major
        float4* xv = reinterpret_cast<float4*>(data + (tid & 7) * PITCH);
        const int bi0 = tid >> 3;
        #pragma unroll
        for (int u = 0; u < 4; u++) {
            const int bi = bi0 + (u << 6);
            float4 f01 = xv[2 * bi];
            float4 f23 = xv[2 * bi + 1];
            float2 y0, y1, y2, y3;
            rad4(make_float2(f01.x, f01.y), make_float2(f01.z, f01.w),
                 make_float2(f23.x, f23.y), make_float2(f23.z, f23.w),
                 y0, y1, y2, y3);
            xv[2 * bi]     = make_float4(y0.x, y0.y, y1.x, y1.y);
            xv[2 * bi + 1] = make_float4(y2.x, y2.y, y3.x, y3.y);
        }
        __syncthreads();
    }
    stage4<1, TW_OFF1>(data + (tid & 7) * PITCH, tw, tid >> 3);
    __syncthreads();
    stage4<2, TW_OFF2>(data + (tid >> 6) * PITCH, tw, tid & 63);
    __syncthreads();
    stage4<3, TW_OFF3>(data + (tid >> 6) * PITCH, tw, tid & 63);
    __syncthreads();
    stage4_last_pruned(data + (tid >> 6) * PITCH, tw, tid & 63);
    __syncthreads();
}

// ---------------------------------------------------------------------------
__global__ __launch_bounds__(512, 3)
void fft_x_kernel()
{
    extern __shared__ float2 sm[];
    float2* tw   = sm;
    float2* data = sm + TW_TOT;
    const int tid = threadIdx.x;
    init_tw(tw, tid, 512);

    const int iy = blockIdx.x;

    for (int t = tid; t < 8 * KGRID; t += 512) {
        int ix = t >> 3;
        int c  = t & 7;
        data[c * PITCH + digit_rev10(ix)] =
            g_grid[ix * (KGRID * BATCH) + iy * BATCH + c];
    }
    __syncthreads();

    fft8x1024(data, tw, tid);

    for (int t = tid; t < 8 * 512; t += 512) {
        int xl = t >> 3;
        int c  = t & 7;
        int xg = (xl < 256) ? xl : xl + 512;   // rows kept after shift+crop
        g_grid[xg * (KGRID * BATCH) + iy * BATCH + c] = data[c * PITCH + xg];
    }
}

// ---------------------------------------------------------------------------
__device__ __forceinline__ float inv_apod(int i)
{
    float xv = ((float)i - 256.0f) * (1.0f / 1024.0f);
    float pj = PI_F * 6.0f * xv;
    float tv = BETA_F * BETA_F - pj * pj;
    float st = sqrtf(fabsf(tv));
    float num = (tv > 0.0f) ? sinhf(st) : sinf(st);
    return fmaxf(st, 1e-6f) / num;
}

__global__ __launch_bounds__(512, 3)
void fft_y_kernel(float* __restrict__ out)
{
    extern __shared__ float2 sm[];
    float2* tw   = sm;
    float2* data = sm + TW_TOT;
    const int tid = threadIdx.x;
    init_tw(tw, tid, 512);

    const int x_img = blockIdx.x;
    const int x_src = (x_img + 768) & (KGRID - 1);
    const float2* grow = &g_grid[x_src * (KGRID * BATCH)];

    for (int t = tid; t < 8 * KGRID; t += 512) {
        int iy = t >> 3;
        int c  = t & 7;
        data[c * PITCH + digit_rev10(iy)] = grow[t];
    }
    __syncthreads();

    fft8x1024(data, tw, tid);

    const float iax = inv_apod(x_img);
    for (int t = tid; t < 8 * NIMG; t += 512) {
        int b  = t >> 9;
        int yi = t & 511;
        int ys = (yi + 768) & (KGRID - 1);     // in [0,256) U [768,1024)
        float v = data[b * PITCH + ys].x;
        out[b * (NIMG * NIMG) + x_img * NIMG + yi] = v * iax * inv_apod(yi);
    }
}

// ---------------------------------------------------------------------------
extern "C" void kernel_launch(void* const* d_in, const int* in_sizes, int n_in,
                              void* d_out, int out_size)
{
    const float* yr  = (const float*)d_in[0];
    const float* yi  = (const float*)d_in[1];
    const float* uv  = (const float*)d_in[2];
    const float* wts = (const float*)d_in[3];
    float* out = (float*)d_out;

    const int smem_fft = (TW_TOT + 8 * PITCH) * (int)sizeof(float2); // ~73.8 KB
    cudaFuncSetAttribute(fft_x_kernel,
                         cudaFuncAttributeMaxDynamicSharedMemorySize, smem_fft);
    cudaFuncSetAttribute(fft_y_kernel,
                         cudaFuncAttributeMaxDynamicSharedMemorySize, smem_fft);

    zero_kernel<<<4096, 256>>>();
    scatter_kernel<<<(4 * MPTS + 255) / 256, 256>>>(yr, yi, uv, wts);
    fft_x_kernel<<<KGRID, 512, smem_fft>>>();
    fft_y_kernel<<<NIMG, 512, smem_fft>>>(out);
}

// round 8
// speedup vs baseline: 2.5555x; 1.0196x over previous
#include <cuda_runtime.h>
#include <math.h>

// ---------------------------------------------------------------------------
// NUFFT adjoint (Kaiser-Bessel gridding) for GB300 — round 8
// = R7 (zero prefetch + radix-4 pruned FFTs)
// + scatter split 8-ways per point: (batch pair q) x (x-tap half h),
//   18 red.v4 per thread, for deeper atomic memory-level parallelism.
// ---------------------------------------------------------------------------

#define KGRID   1024
#define NIMG    512
#define MPTS    200000
#define BATCH   8
#define JW      6
#define BETA_F  14.04f
#define PI_F    3.14159265358979f

#define GRID_F2 (KGRID * KGRID * BATCH)   // 64 MB
#define PITCH   1026                      // smem row pitch (float2), even

#define TW_OFF1 0
#define TW_OFF2 12
#define TW_OFF3 60
#define TW_OFF4 252
#define TW_TOT  1020

__device__ float2 g_grid[GRID_F2];

// ---------------------------------------------------------------------------
__device__ __forceinline__ float bessel_i0(float x)
{
    if (x < 3.75f) {
        float t = x * (1.0f / 3.75f);
        t *= t;
        return 1.0f + t * (3.5156229f + t * (3.0899424f + t * (1.2067492f +
                     t * (0.2659732f + t * (0.0360768f + t * 0.0045813f)))));
    } else {
        float t = 3.75f / x;
        float p = 0.39894228f + t * (0.01328592f + t * (0.00225319f +
                  t * (-0.00157565f + t * (0.00916281f + t * (-0.02057706f +
                  t * (0.02635537f + t * (-0.01647633f + t * 0.00392377f)))))));
        return __expf(x) * rsqrtf(x) * p;
    }
}

// ---------------------------------------------------------------------------
// Zero the oversampled grid. Also acts as an L2 warm for the scatter's
// atomics: all 64 MB become dirty-zero L2 lines (load-bearing — see R6).
// ---------------------------------------------------------------------------
__global__ void zero_kernel()
{
    float4* p = reinterpret_cast<float4*>(g_grid);
    const int n = GRID_F2 / 2;
    for (int i = blockIdx.x * blockDim.x + threadIdx.x; i < n;
         i += gridDim.x * blockDim.x)
        p[i] = make_float4(0.f, 0.f, 0.f, 0.f);
}

// ---------------------------------------------------------------------------
// Gridding scatter: 8 threads per measurement.
//   q = batch pair (2 batches), h = x-tap half (3 of 6 a-values)
//   -> 18 red.v4.f32 per thread.
// ---------------------------------------------------------------------------
__global__ __launch_bounds__(256)
void scatter_kernel(const float* __restrict__ yr, const float* __restrict__ yi,
                    const float* __restrict__ uv, const float* __restrict__ wts)
{
    const int gid = blockIdx.x * blockDim.x + threadIdx.x;
    const int m = gid >> 3;
    const int q = gid & 3;                 // batches 2q, 2q+1
    const int h = (gid >> 2) & 1;          // a in {3h, 3h+1, 3h+2}
    if (m >= MPTS) return;

    const float2 c2 = reinterpret_cast<const float2*>(uv)[m];
    const float wt = wts[m];
    const float inv_i0b = 1.0f / bessel_i0(BETA_F);

    int ixv[3], iyv[JW];
    float wx[3], wy[JW];

    {   // axis 0: only this thread's 3 taps
        float k  = c2.x / (2.0f * PI_F) * (float)KGRID;
        float km = floorf(k - 3.0f);
        #pragma unroll
        for (int j = 0; j < 3; j++) {
            int jj = 3 * h + j;
            float pt = km + (float)(jj + 1);
            float d  = k - pt;
            float arg = fmaxf(1.0f - d * d * (1.0f / 9.0f), 0.0f);
            wx[j] = bessel_i0(BETA_F * sqrtf(arg)) * inv_i0b;
            ixv[j] = ((int)pt + KGRID) & (KGRID - 1);
        }
    }
    {   // axis 1: all 6 taps
        float k  = c2.y / (2.0f * PI_F) * (float)KGRID;
        float km = floorf(k - 3.0f);
        #pragma unroll
        for (int j = 0; j < JW; j++) {
            float pt = km + (float)(j + 1);
            float d  = k - pt;
            float arg = fmaxf(1.0f - d * d * (1.0f / 9.0f), 0.0f);
            wy[j] = bessel_i0(BETA_F * sqrtf(arg)) * inv_i0b;
            iyv[j] = ((int)pt + KGRID) & (KGRID - 1);
        }
    }

    const int b0 = 2 * q;
    const float yr0 = yr[b0 * MPTS + m] * wt;
    const float yi0 = yi[b0 * MPTS + m] * wt;
    const float yr1 = yr[(b0 + 1) * MPTS + m] * wt;
    const float yi1 = yi[(b0 + 1) * MPTS + m] * wt;

    #pragma unroll
    for (int a = 0; a < 3; a++) {
        const int rowbase = ixv[a] * KGRID;
        const float wxa = wx[a];
        #pragma unroll
        for (int c = 0; c < JW; c++) {
            const float w2 = wxa * wy[c];
            float* fp = reinterpret_cast<float*>(&g_grid[(rowbase + iyv[c]) * BATCH])
                        + 4 * q;
            asm volatile(
                "red.global.add.v4.f32 [%0], {%1, %2, %3, %4};"
                :: "l"(fp),
                   "f"(w2 * yr0), "f"(w2 * yi0),
                   "f"(w2 * yr1), "f"(w2 * yi1)
                : "memory");
        }
    }
}

// ---------------------------------------------------------------------------
// Radix-4 FFT machinery (inverse, e^{+i})
// ---------------------------------------------------------------------------
__device__ __forceinline__ int digit_rev10(int i)
{
    int r = (int)(__brev((unsigned)i) >> 22);
    return ((r & 0x155) << 1) | ((r & 0x2AA) >> 1);
}

__device__ __forceinline__ float2 cmul(float2 a, float2 b)
{
    return make_float2(a.x * b.x - a.y * b.y, a.x * b.y + a.y * b.x);
}

__device__ __forceinline__ void init_tw(float2* tw, int tid, int nthr)
{
    for (int t = tid; t < 340; t += nthr) {
        int s, j, off;
        if      (t < 4)  { s = 1; j = t;      off = TW_OFF1; }
        else if (t < 20) { s = 2; j = t - 4;  off = TW_OFF2; }
        else if (t < 84) { s = 3; j = t - 20; off = TW_OFF3; }
        else             { s = 4; j = t - 84; off = TW_OFF4; }
        int em = j << (8 - 2 * s);
        float a = (float)em * (2.0f * PI_F / 1024.0f);
        float s1, c1, s2, c2, s3, c3;
        __sincosf(a, &s1, &c1);
        __sincosf(2.0f * a, &s2, &c2);
        __sincosf(3.0f * a, &s3, &c3);
        tw[off + 3 * j + 0] = make_float2(c1, s1);
        tw[off + 3 * j + 1] = make_float2(c2, s2);
        tw[off + 3 * j + 2] = make_float2(c3, s3);
    }
}

__device__ __forceinline__ void rad4(float2 b0, float2 b1, float2 b2, float2 b3,
                                     float2& y0, float2& y1, float2& y2, float2& y3)
{
    float2 t0 = make_float2(b0.x + b2.x, b0.y + b2.y);
    float2 t1 = make_float2(b0.x - b2.x, b0.y - b2.y);
    float2 t2 = make_float2(b1.x + b3.x, b1.y + b3.y);
    float2 t3 = make_float2(-(b1.y - b3.y), b1.x - b3.x);   // +i*(b1-b3)
    y0 = make_float2(t0.x + t2.x, t0.y + t2.y);
    y1 = make_float2(t1.x + t3.x, t1.y + t3.y);
    y2 = make_float2(t0.x - t2.x, t0.y - t2.y);
    y3 = make_float2(t1.x - t3.x, t1.y - t3.y);
}

template<int S, int OFF>
__device__ __forceinline__ void stage4(float2* x, const float2* tw, int bi0)
{
    const int sh = 2 * S;
    const int quarter = 1 << sh;
    #pragma unroll
    for (int u = 0; u < 4; u++) {
        const int bi = bi0 + (u << 6);
        const int j  = bi & (quarter - 1);
        const int base = ((bi >> sh) << (sh + 2)) | j;
        float2 b0 = x[base];
        float2 b1 = x[base + quarter];
        float2 b2 = x[base + 2 * quarter];
        float2 b3 = x[base + 3 * quarter];
        b1 = cmul(b1, tw[OFF + 3 * j + 0]);
        b2 = cmul(b2, tw[OFF + 3 * j + 1]);
        b3 = cmul(b3, tw[OFF + 3 * j + 2]);
        float2 y0, y1, y2, y3;
        rad4(b0, b1, b2, b3, y0, y1, y2, y3);
        x[base]               = y0;
        x[base + quarter]     = y1;
        x[base + 2 * quarter] = y2;
        x[base + 3 * quarter] = y3;
    }
}

// Final stage (S=4), pruned to the fftshift+crop-surviving halves.
__device__ __forceinline__ void stage4_last_pruned(float2* x, const float2* tw,
                                                   int bi0)
{
    const int quarter = 256;
    #pragma unroll
    for (int u = 0; u < 4; u++) {
        const int j = bi0 + (u << 6);          // base == j for S=4
        float2 b0 = x[j];
        float2 b1 = cmul(x[j + quarter],     tw[TW_OFF4 + 3 * j + 0]);
        float2 b2 = cmul(x[j + 2 * quarter], tw[TW_OFF4 + 3 * j + 1]);
        float2 b3 = cmul(x[j + 3 * quarter], tw[TW_OFF4 + 3 * j + 2]);
        float2 t0 = make_float2(b0.x + b2.x, b0.y + b2.y);
        float2 t1 = make_float2(b0.x - b2.x, b0.y - b2.y);
        float2 t2 = make_float2(b1.x + b3.x, b1.y + b3.y);
        float2 t3 = make_float2(-(b1.y - b3.y), b1.x - b3.x);
        x[j]               = make_float2(t0.x + t2.x, t0.y + t2.y);  // y0
        x[j + 3 * quarter] = make_float2(t1.x - t3.x, t1.y - t3.y);  // y3
    }
}

__device__ __forceinline__ void fft8x1024(float2* data, const float2* tw, int tid)
{
    {   // stage 0: float4-vectorized, twiddle-free, fft-major
        float4* xv = reinterpret_cast<float4*>(data + (tid & 7) * PITCH);
        const int bi0 = tid >> 3;
        #pragma unroll
        for (int u = 0; u < 4; u++) {
            const int bi = bi0 + (u << 6);
            float4 f01 = xv[2 * bi];
            float4 f23 = xv[2 * bi + 1];
            float2 y0, y1, y2, y3;
            rad4(make_float2(f01.x, f01.y), make_float2(f01.z, f01.w),
                 make_float2(f23.x, f23.y), make_float2(f23.z, f23.w),
                 y0, y1, y2, y3);
            xv[2 * bi]     = make_float4(y0.x, y0.y, y1.x, y1.y);
            xv[2 * bi + 1] = make_float4(y2.x, y2.y, y3.x, y3.y);
        }
        __syncthreads();
    }
    stage4<1, TW_OFF1>(data + (tid & 7) * PITCH, tw, tid >> 3);
    __syncthreads();
    stage4<2, TW_OFF2>(data + (tid >> 6) * PITCH, tw, tid & 63);
    __syncthreads();
    stage4<3, TW_OFF3>(data + (tid >> 6) * PITCH, tw, tid & 63);
    __syncthreads();
    stage4_last_pruned(data + (tid >> 6) * PITCH, tw, tid & 63);
    __syncthreads();
}

// ---------------------------------------------------------------------------
__global__ __launch_bounds__(512, 3)
void fft_x_kernel()
{
    extern __shared__ float2 sm[];
    float2* tw   = sm;
    float2* data = sm + TW_TOT;
    const int tid = threadIdx.x;
    init_tw(tw, tid, 512);

    const int iy = blockIdx.x;

    for (int t = tid; t < 8 * KGRID; t += 512) {
        int ix = t >> 3;
        int c  = t & 7;
        data[c * PITCH + digit_rev10(ix)] =
            g_grid[ix * (KGRID * BATCH) + iy * BATCH + c];
    }
    __syncthreads();

    fft8x1024(data, tw, tid);

    for (int t = tid; t < 8 * 512; t += 512) {
        int xl = t >> 3;
        int c  = t & 7;
        int xg = (xl < 256) ? xl : xl + 512;   // rows kept after shift+crop
        g_grid[xg * (KGRID * BATCH) + iy * BATCH + c] = data[c * PITCH + xg];
    }
}

// ---------------------------------------------------------------------------
__device__ __forceinline__ float inv_apod(int i)
{
    float xv = ((float)i - 256.0f) * (1.0f / 1024.0f);
    float pj = PI_F * 6.0f * xv;
    float tv = BETA_F * BETA_F - pj * pj;
    float st = sqrtf(fabsf(tv));
    float num = (tv > 0.0f) ? sinhf(st) : sinf(st);
    return fmaxf(st, 1e-6f) / num;
}

__global__ __launch_bounds__(512, 3)
void fft_y_kernel(float* __restrict__ out)
{
    extern __shared__ float2 sm[];
    float2* tw   = sm;
    float2* data = sm + TW_TOT;
    const int tid = threadIdx.x;
    init_tw(tw, tid, 512);

    const int x_img = blockIdx.x;
    const int x_src = (x_img + 768) & (KGRID - 1);
    const float2* grow = &g_grid[x_src * (KGRID * BATCH)];

    for (int t = tid; t < 8 * KGRID; t += 512) {
        int iy = t >> 3;
        int c  = t & 7;
        data[c * PITCH + digit_rev10(iy)] = grow[t];
    }
    __syncthreads();

    fft8x1024(data, tw, tid);

    const float iax = inv_apod(x_img);
    for (int t = tid; t < 8 * NIMG; t += 512) {
        int b  = t >> 9;
        int yi = t & 511;
        int ys = (yi + 768) & (KGRID - 1);     // in [0,256) U [768,1024)
        float v = data[b * PITCH + ys].x;
        out[b * (NIMG * NIMG) + x_img * NIMG + yi] = v * iax * inv_apod(yi);
    }
}

// ---------------------------------------------------------------------------
extern "C" void kernel_launch(void* const* d_in, const int* in_sizes, int n_in,
                              void* d_out, int out_size)
{
    const float* yr  = (const float*)d_in[0];
    const float* yi  = (const float*)d_in[1];
    const float* uv  = (const float*)d_in[2];
    const float* wts = (const float*)d_in[3];
    float* out = (float*)d_out;

    const int smem_fft = (TW_TOT + 8 * PITCH) * (int)sizeof(float2); // ~73.8 KB
    cudaFuncSetAttribute(fft_x_kernel,
                         cudaFuncAttributeMaxDynamicSharedMemorySize, smem_fft);
    cudaFuncSetAttribute(fft_y_kernel,
                         cudaFuncAttributeMaxDynamicSharedMemorySize, smem_fft);

    zero_kernel<<<4096, 256>>>();
    scatter_kernel<<<(8 * MPTS + 255) / 256, 256>>>(yr, yi, uv, wts);
    fft_x_kernel<<<KGRID, 512, smem_fft>>>();
    fft_y_kernel<<<NIMG, 512, smem_fft>>>(out);
}

// round 9
// speedup vs baseline: 2.8242x; 1.1051x over previous
#include <cuda_runtime.h>
#include <math.h>

// ---------------------------------------------------------------------------
// NUFFT adjoint (Kaiser-Bessel gridding) for GB300 — round 9
// = R8 (zero L2-warm + 8-way scatter + radix-4 pruned FFTs)
// + Hermitian batch-pairing: Re(IFFT2 G) = IFFT2(He(G)), so batches (2p,2p+1)
//   pack into ONE complex transform C_p = He(G_2p) + i He(G_2p+1).
//   FFT work halves: fft_x = 513 column-pair blocks (8 FFTs -> 2 columns),
//   fft_y = 256 blocks (2 rows x 4 packed FFTs), epilogue Re/Im split.
// ---------------------------------------------------------------------------

#define KGRID   1024
#define NIMG    512
#define MPTS    200000
#define BATCH   8
#define JW      6
#define BETA_F  14.04f
#define PI_F    3.14159265358979f

#define GRID_F2 (KGRID * KGRID * BATCH)   // 64 MB
#define PITCH   1026                      // smem row pitch (float2), even

#define TW_OFF1 0
#define TW_OFF2 12
#define TW_OFF3 60
#define TW_OFF4 252
#define TW_TOT  1020

__device__ float2 g_grid[GRID_F2];

// ---------------------------------------------------------------------------
__device__ __forceinline__ float bessel_i0(float x)
{
    if (x < 3.75f) {
        float t = x * (1.0f / 3.75f);
        t *= t;
        return 1.0f + t * (3.5156229f + t * (3.0899424f + t * (1.2067492f +
                     t * (0.2659732f + t * (0.0360768f + t * 0.0045813f)))));
    } else {
        float t = 3.75f / x;
        float p = 0.39894228f + t * (0.01328592f + t * (0.00225319f +
                  t * (-0.00157565f + t * (0.00916281f + t * (-0.02057706f +
                  t * (0.02635537f + t * (-0.01647633f + t * 0.00392377f)))))));
        return __expf(x) * rsqrtf(x) * p;
    }
}

// ---------------------------------------------------------------------------
// Zero the grid. Also the L2 warm for the scatter's atomics (load-bearing).
// ---------------------------------------------------------------------------
__global__ void zero_kernel()
{
    float4* p = reinterpret_cast<float4*>(g_grid);
    const int n = GRID_F2 / 2;
    for (int i = blockIdx.x * blockDim.x + threadIdx.x; i < n;
         i += gridDim.x * blockDim.x)
        p[i] = make_float4(0.f, 0.f, 0.f, 0.f);
}

// ---------------------------------------------------------------------------
// Gridding scatter: 8 threads per measurement (batch pair x tap half).
// ---------------------------------------------------------------------------
__global__ __launch_bounds__(256)
void scatter_kernel(const float* __restrict__ yr, const float* __restrict__ yi,
                    const float* __restrict__ uv, const float* __restrict__ wts)
{
    const int gid = blockIdx.x * blockDim.x + threadIdx.x;
    const int m = gid >> 3;
    const int q = gid & 3;                 // batches 2q, 2q+1
    const int h = (gid >> 2) & 1;          // a in {3h, 3h+1, 3h+2}
    if (m >= MPTS) return;

    const float2 c2 = reinterpret_cast<const float2*>(uv)[m];
    const float wt = wts[m];
    const float inv_i0b = 1.0f / bessel_i0(BETA_F);

    int ixv[3], iyv[JW];
    float wx[3], wy[JW];

    {
        float k  = c2.x / (2.0f * PI_F) * (float)KGRID;
        float km = floorf(k - 3.0f);
        #pragma unroll
        for (int j = 0; j < 3; j++) {
            int jj = 3 * h + j;
            float pt = km + (float)(jj + 1);
            float d  = k - pt;
            float arg = fmaxf(1.0f - d * d * (1.0f / 9.0f), 0.0f);
            wx[j] = bessel_i0(BETA_F * sqrtf(arg)) * inv_i0b;
            ixv[j] = ((int)pt + KGRID) & (KGRID - 1);
        }
    }
    {
        float k  = c2.y / (2.0f * PI_F) * (float)KGRID;
        float km = floorf(k - 3.0f);
        #pragma unroll
        for (int j = 0; j < JW; j++) {
            float pt = km + (float)(j + 1);
            float d  = k - pt;
            float arg = fmaxf(1.0f - d * d * (1.0f / 9.0f), 0.0f);
            wy[j] = bessel_i0(BETA_F * sqrtf(arg)) * inv_i0b;
            iyv[j] = ((int)pt + KGRID) & (KGRID - 1);
        }
    }

    const int b0 = 2 * q;
    const float yr0 = yr[b0 * MPTS + m] * wt;
    const float yi0 = yi[b0 * MPTS + m] * wt;
    const float yr1 = yr[(b0 + 1) * MPTS + m] * wt;
    const float yi1 = yi[(b0 + 1) * MPTS + m] * wt;

    #pragma unroll
    for (int a = 0; a < 3; a++) {
        const int rowbase = ixv[a] * KGRID;
        const float wxa = wx[a];
        #pragma unroll
        for (int c = 0; c < JW; c++) {
            const float w2 = wxa * wy[c];
            float* fp = reinterpret_cast<float*>(&g_grid[(rowbase + iyv[c]) * BATCH])
                        + 4 * q;
            asm volatile(
                "red.global.add.v4.f32 [%0], {%1, %2, %3, %4};"
                :: "l"(fp),
                   "f"(w2 * yr0), "f"(w2 * yi0),
                   "f"(w2 * yr1), "f"(w2 * yi1)
                : "memory");
        }
    }
}

// ---------------------------------------------------------------------------
// Radix-4 FFT machinery (inverse, e^{+i})
// ---------------------------------------------------------------------------
__device__ __forceinline__ int digit_rev10(int i)
{
    int r = (int)(__brev((unsigned)i) >> 22);
    return ((r & 0x155) << 1) | ((r & 0x2AA) >> 1);
}

__device__ __forceinline__ float2 cmul(float2 a, float2 b)
{
    return make_float2(a.x * b.x - a.y * b.y, a.x * b.y + a.y * b.x);
}

__device__ __forceinline__ void init_tw(float2* tw, int tid, int nthr)
{
    for (int t = tid; t < 340; t += nthr) {
        int s, j, off;
        if      (t < 4)  { s = 1; j = t;      off = TW_OFF1; }
        else if (t < 20) { s = 2; j = t - 4;  off = TW_OFF2; }
        else if (t < 84) { s = 3; j = t - 20; off = TW_OFF3; }
        else             { s = 4; j = t - 84; off = TW_OFF4; }
        int em = j << (8 - 2 * s);
        float a = (float)em * (2.0f * PI_F / 1024.0f);
        float s1, c1, s2, c2, s3, c3;
        __sincosf(a, &s1, &c1);
        __sincosf(2.0f * a, &s2, &c2);
        __sincosf(3.0f * a, &s3, &c3);
        tw[off + 3 * j + 0] = make_float2(c1, s1);
        tw[off + 3 * j + 1] = make_float2(c2, s2);
        tw[off + 3 * j + 2] = make_float2(c3, s3);
    }
}

__device__ __forceinline__ void rad4(float2 b0, float2 b1, float2 b2, float2 b3,
                                     float2& y0, float2& y1, float2& y2, float2& y3)
{
    float2 t0 = make_float2(b0.x + b2.x, b0.y + b2.y);
    float2 t1 = make_float2(b0.x - b2.x, b0.y - b2.y);
    float2 t2 = make_float2(b1.x + b3.x, b1.y + b3.y);
    float2 t3 = make_float2(-(b1.y - b3.y), b1.x - b3.x);   // +i*(b1-b3)
    y0 = make_float2(t0.x + t2.x, t0.y + t2.y);
    y1 = make_float2(t1.x + t3.x, t1.y + t3.y);
    y2 = make_float2(t0.x - t2.x, t0.y - t2.y);
    y3 = make_float2(t1.x - t3.x, t1.y - t3.y);
}

template<int S, int OFF>
__device__ __forceinline__ void stage4(float2* x, const float2* tw, int bi0)
{
    const int sh = 2 * S;
    const int quarter = 1 << sh;
    #pragma unroll
    for (int u = 0; u < 4; u++) {
        const int bi = bi0 + (u << 6);
        const int j  = bi & (quarter - 1);
        const int base = ((bi >> sh) << (sh + 2)) | j;
        float2 b0 = x[base];
        float2 b1 = x[base + quarter];
        float2 b2 = x[base + 2 * quarter];
        float2 b3 = x[base + 3 * quarter];
        b1 = cmul(b1, tw[OFF + 3 * j + 0]);
        b2 = cmul(b2, tw[OFF + 3 * j + 1]);
        b3 = cmul(b3, tw[OFF + 3 * j + 2]);
        float2 y0, y1, y2, y3;
        rad4(b0, b1, b2, b3, y0, y1, y2, y3);
        x[base]               = y0;
        x[base + quarter]     = y1;
        x[base + 2 * quarter] = y2;
        x[base + 3 * quarter] = y3;
    }
}

// Final stage (S=4), pruned to the fftshift+crop-surviving halves.
__device__ __forceinline__ void stage4_last_pruned(float2* x, const float2* tw,
                                                   int bi0)
{
    const int quarter = 256;
    #pragma unroll
    for (int u = 0; u < 4; u++) {
        const int j = bi0 + (u << 6);          // base == j for S=4
        float2 b0 = x[j];
        float2 b1 = cmul(x[j + quarter],     tw[TW_OFF4 + 3 * j + 0]);
        float2 b2 = cmul(x[j + 2 * quarter], tw[TW_OFF4 + 3 * j + 1]);
        float2 b3 = cmul(x[j + 3 * quarter], tw[TW_OFF4 + 3 * j + 2]);
        float2 t0 = make_float2(b0.x + b2.x, b0.y + b2.y);
        float2 t1 = make_float2(b0.x - b2.x, b0.y - b2.y);
        float2 t2 = make_float2(b1.x + b3.x, b1.y + b3.y);
        float2 t3 = make_float2(-(b1.y - b3.y), b1.x - b3.x);
        x[j]               = make_float2(t0.x + t2.x, t0.y + t2.y);  // y0
        x[j + 3 * quarter] = make_float2(t1.x - t3.x, t1.y - t3.y);  // y3
    }
}

__device__ __forceinline__ void fft8x1024(float2* data, const float2* tw, int tid)
{
    {   // stage 0: float4-vectorized, twiddle-free, fft-major
        float4* xv = reinterpret_cast<float4*>(data + (tid & 7) * PITCH);
        const int bi0 = tid >> 3;
        #pragma unroll
        for (int u = 0; u < 4; u++) {
            const int bi = bi0 + (u << 6);
            float4 f01 = xv[2 * bi];
            float4 f23 = xv[2 * bi + 1];
            float2 y0, y1, y2, y3;
            rad4(make_float2(f01.x, f01.y), make_float2(f01.z, f01.w),
                 make_float2(f23.x, f23.y), make_float2(f23.z, f23.w),
                 y0, y1, y2, y3);
            xv[2 * bi]     = make_float4(y0.x, y0.y, y1.x, y1.y);
            xv[2 * bi + 1] = make_float4(y2.x, y2.y, y3.x, y3.y);
        }
        __syncthreads();
    }
    stage4<1, TW_OFF1>(data + (tid & 7) * PITCH, tw, tid >> 3);
    __syncthreads();
    stage4<2, TW_OFF2>(data + (tid >> 6) * PITCH, tw, tid & 63);
    __syncthreads();
    stage4<3, TW_OFF3>(data + (tid >> 6) * PITCH, tw, tid & 63);
    __syncthreads();
    stage4_last_pruned(data + (tid >> 6) * PITCH, tw, tid & 63);
    __syncthreads();
}

// ---------------------------------------------------------------------------
// FFT along kx on Hermitian-packed batch pairs.
// Block = column pair (iy, iyr=(K-iy)&(K-1)); 513 blocks, iy = 0..512.
// smem rows 0-3: output column iy,  p = 0..3 (batches 2p, 2p+1 packed)
//       rows 4-7: output column iyr, p = 0..3
// Packed input: C_p(ix,col) = He(G_2p)(ix,col) + i He(G_2p+1)(ix,col)
//   where He(G)(ix,col) = 0.5 (G(ix,col) + conj(G(-ix,-col))).
// Each column is read by exactly one block; packed output goes to batch
// slots 0..3 of the surviving rows (slots 4..7 become stale; zero_kernel
// rewrites everything next launch).
// ---------------------------------------------------------------------------
__global__ __launch_bounds__(512, 3)
void fft_x_kernel()
{
    extern __shared__ float2 sm[];
    float2* tw   = sm;
    float2* data = sm + TW_TOT;
    const int tid = threadIdx.x;
    init_tw(tw, tid, 512);

    const int iy  = blockIdx.x;                       // 0..512
    const int iyr = (KGRID - iy) & (KGRID - 1);

    for (int t = tid; t < 8 * KGRID; t += 512) {
        int ix  = t >> 3;
        int r   = t & 7;
        int p   = r & 3;
        int colA = (r < 4) ? iy : iyr;
        int colB = (r < 4) ? iyr : iy;
        int ixr = (KGRID - ix) & (KGRID - 1);
        // A = (G_{2p}, G_{2p+1}) at (ix, colA); B = same pair at (-ix, -colA)
        const float4 A = *reinterpret_cast<const float4*>(
            &g_grid[(ix  * KGRID + colA) * BATCH + 2 * p]);
        const float4 B = *reinterpret_cast<const float4*>(
            &g_grid[(ixr * KGRID + colB) * BATCH + 2 * p]);
        float2 c;
        c.x = 0.5f * ((A.x + B.x) - (A.w - B.w));
        c.y = 0.5f * ((A.y - B.y) + (A.z + B.z));
        data[r * PITCH + digit_rev10(ix)] = c;
    }
    __syncthreads();

    fft8x1024(data, tw, tid);

    for (int t = tid; t < 8 * 512; t += 512) {
        int xl = t >> 3;
        int r  = t & 7;
        int p  = r & 3;
        int col = (r < 4) ? iy : iyr;
        int xg = (xl < 256) ? xl : xl + 512;   // rows kept after shift+crop
        g_grid[(xg * KGRID + col) * BATCH + p] = data[r * PITCH + xg];
    }
}

// ---------------------------------------------------------------------------
__device__ __forceinline__ float inv_apod(int i)
{
    float xv = ((float)i - 256.0f) * (1.0f / 1024.0f);
    float pj = PI_F * 6.0f * xv;
    float tv = BETA_F * BETA_F - pj * pj;
    float st = sqrtf(fabsf(tv));
    float num = (tv > 0.0f) ? sinhf(st) : sinf(st);
    return fmaxf(st, 1e-6f) / num;
}

// FFT along ky on packed data: 2 x rows x 4 packed FFTs per block; 256 blocks.
// Epilogue: batch 2p = Re, batch 2p+1 = Im, with fftshift/crop/deapod.
__global__ __launch_bounds__(512, 3)
void fft_y_kernel(float* __restrict__ out)
{
    extern __shared__ float2 sm[];
    float2* tw   = sm;
    float2* data = sm + TW_TOT;
    const int tid = threadIdx.x;
    init_tw(tw, tid, 512);

    const int x_img0 = blockIdx.x * 2;

    for (int t = tid; t < 8 * KGRID; t += 512) {
        int ky = t >> 3;
        int r  = t & 7;                        // r = xl*4 + p
        int xl = r >> 2;
        int p  = r & 3;
        int x_src = ((x_img0 + xl) + 768) & (KGRID - 1);
        data[r * PITCH + digit_rev10(ky)] =
            g_grid[(x_src * KGRID + ky) * BATCH + p];
    }
    __syncthreads();

    fft8x1024(data, tw, tid);

    const float iax0 = inv_apod(x_img0);
    const float iax1 = inv_apod(x_img0 + 1);
    for (int t = tid; t < 8 * NIMG; t += 512) {
        int r  = t >> 9;                       // 0..7 = xl*4 + p
        int yi = t & 511;
        int xl = r >> 2;
        int p  = r & 3;
        int ys = (yi + 768) & (KGRID - 1);     // in [0,256) U [768,1024)
        float2 v = data[r * PITCH + ys];
        float scale = (xl ? iax1 : iax0) * inv_apod(yi);
        int xi = x_img0 + xl;
        out[(2 * p)     * (NIMG * NIMG) + xi * NIMG + yi] = v.x * scale;
        out[(2 * p + 1) * (NIMG * NIMG) + xi * NIMG + yi] = v.y * scale;
    }
}

// ---------------------------------------------------------------------------
extern "C" void kernel_launch(void* const* d_in, const int* in_sizes, int n_in,
                              void* d_out, int out_size)
{
    const float* yr  = (const float*)d_in[0];
    const float* yi  = (const float*)d_in[1];
    const float* uv  = (const float*)d_in[2];
    const float* wts = (const float*)d_in[3];
    float* out = (float*)d_out;

    const int smem_fft = (TW_TOT + 8 * PITCH) * (int)sizeof(float2); // ~73.8 KB
    cudaFuncSetAttribute(fft_x_kernel,
                         cudaFuncAttributeMaxDynamicSharedMemorySize, smem_fft);
    cudaFuncSetAttribute(fft_y_kernel,
                         cudaFuncAttributeMaxDynamicSharedMemorySize, smem_fft);

    zero_kernel<<<4096, 256>>>();
    scatter_kernel<<<(8 * MPTS + 255) / 256, 256>>>(yr, yi, uv, wts);
    fft_x_kernel<<<KGRID / 2 + 1, 512, smem_fft>>>();
    fft_y_kernel<<<NIMG / 2, 512, smem_fft>>>(out);
}